// round 5
// baseline (speedup 1.0000x reference)
#include <cuda_runtime.h>
#include <cuda_fp16.h>
#include <cstdint>

#define NROW 4096
#define DDIM 512
#define CAP  160   // max members per class (mean 64, sd ~8; 160 = +12 sigma)

// -------------------------- device scratch (no allocs) ----------------------
__device__ float g_sq[NROW];
__device__ float g_rowmax[NROW];   // max_distance per row (atomicMax, reset each replay)
__device__ float g_negmin[NROW];   // min dist over different-label j (atomicMin)
__device__ float g_posmax[NROW];   // hardest positive (class kernel, fp32)
__device__ float g_pen[NROW];      // relu(margin - hardest_negative)
__device__ __half g_h[(size_t)NROW * DDIM];   // fp16 features

// -------------------------- PTX helpers -------------------------------------
__device__ __forceinline__ uint32_t smem_u32(const void* p) {
    uint32_t a;
    asm("{ .reg .u64 t; cvta.to.shared.u64 t, %1; cvt.u32.u64 %0, t; }" : "=r"(a) : "l"(p));
    return a;
}

#define CP_ASYNC16(dst, src) \
    asm volatile("cp.async.cg.shared.global [%0], [%1], 16;" :: "r"(dst), "l"(src) : "memory")
#define CP_COMMIT() asm volatile("cp.async.commit_group;" ::: "memory")
#define CP_WAIT(n)  asm volatile("cp.async.wait_group %0;" :: "n"(n) : "memory")

#define LDSM_X4(R, addr) \
    asm volatile("ldmatrix.sync.aligned.m8n8.x4.shared.b16 {%0,%1,%2,%3}, [%4];" \
        : "=r"((R)[0]), "=r"((R)[1]), "=r"((R)[2]), "=r"((R)[3]) : "r"(addr))

// D(16x8,f32) += A(16x16 f16, row) * B(16x8 f16, col: B[n][k])
__device__ __forceinline__ void mma_f16(float* d, const uint32_t* a, uint32_t b0, uint32_t b1) {
    asm volatile(
        "mma.sync.aligned.m16n8k16.row.col.f32.f16.f16.f32 "
        "{%0,%1,%2,%3}, {%4,%5,%6,%7}, {%8,%9}, {%0,%1,%2,%3};"
        : "+f"(d[0]), "+f"(d[1]), "+f"(d[2]), "+f"(d[3])
        : "r"(a[0]), "r"(a[1]), "r"(a[2]), "r"(a[3]), "r"(b0), "r"(b1));
}

// -------------------------- dist kernel SMEM layout -------------------------
// [0]    s_sqi[128]  [512] s_sqj[128]  [1024] s_labi[128]  [1536] s_labj[128]
// [2048] 3 stages x (A[128][40h] + B[128][40h]) fp16   (20480 B per stage)
//        epilogue reuses [2048] as sd[128][132] fp32   (67584 B)
#define SM_SQI   0
#define SM_SQJ   512
#define SM_LABI  1024
#define SM_LABJ  1536
#define SM_BUF   2048
#define ROWB     80                // bytes per smem tile row (32 halves + 8 pad)
#define TILEB    (128 * ROWB)      // 10240
#define STAGE_BYTES (2 * TILEB)    // 20480
#define SMEM_TOTAL (SM_BUF + 128 * 132 * 4)   // 69632 (> 2048 + 3*20480 = 63488)

// ---------------------------------------------------------------------------
// Kernel 0: fp16 convert + squared norms + per-replay stat reset
// ---------------------------------------------------------------------------
__global__ void conv_kernel(const float* __restrict__ X) {
    int row = blockIdx.x;
    int t = threadIdx.x;           // 0..127, one float4 each
    const float4* xr = reinterpret_cast<const float4*>(X + (size_t)row * DDIM);
    float4 v = xr[t];
    float vv[4] = {v.x, v.y, v.z, v.w};
    float s = 0.f;
    __half h[4];
    #pragma unroll
    for (int k = 0; k < 4; k++) { s += vv[k] * vv[k]; h[k] = __float2half_rn(vv[k]); }
    *reinterpret_cast<uint2*>(g_h + (size_t)row * DDIM + t * 4) = *reinterpret_cast<uint2*>(h);
    #pragma unroll
    for (int q = 16; q > 0; q >>= 1) s += __shfl_xor_sync(0xffffffffu, s, q);
    __shared__ float ws[4];
    if ((t & 31) == 0) ws[t >> 5] = s;
    __syncthreads();
    if (t == 0) {
        g_sq[row] = ws[0] + ws[1] + ws[2] + ws[3];
        g_rowmax[row] = 0.f;
        g_negmin[row] = 3.4028235e38f;
    }
}

// ---------------------------------------------------------------------------
// Kernel 1: fp16 mma.sync Gram -> row/col max + diff-label min (no dist store)
// ---------------------------------------------------------------------------
__device__ __forceinline__ void load_chunk(uint32_t stage_base, int m0, int n0, int k0, int tid) {
    #pragma unroll
    for (int t = 0; t < 2; t++) {        // 0 = A rows (m0), 1 = B rows (n0)
        int r0 = t ? n0 : m0;
        uint32_t dbase = stage_base + t * TILEB;
        #pragma unroll
        for (int q = 0; q < 2; q++) {
            int idx = q * 256 + tid;     // 0..511
            int row = idx >> 2;
            int seg = idx & 3;           // 4 x 16B = 32 halves per row
            const __half* gs = g_h + (size_t)(r0 + row) * DDIM + k0 + seg * 8;
            CP_ASYNC16(dbase + (uint32_t)(row * ROWB + seg * 16), gs);
        }
    }
    CP_COMMIT();
}

__global__ __launch_bounds__(256, 2) void dist_kernel(const int* __restrict__ lab) {
    const int bi = blockIdx.y, bj = blockIdx.x;
    if (bj < bi) return;                 // symmetric: upper triangle only
    const int m0 = bi * 128, n0 = bj * 128;
    const bool diag = (bi == bj);

    extern __shared__ char smem[];
    const uint32_t sb = smem_u32(smem);
    const int tid = (int)threadIdx.x;
    const int wid = tid >> 5, lane = tid & 31;
    const int grp = lane >> 2, tig = lane & 3;
    const int mOff = (wid >> 1) * 32;    // warp tile: 32 x 64
    const int nOff = (wid & 1) * 64;
    const int lrow = lane & 15;          // ldmatrix row within 16-row group
    const int lcol = (lane >> 4) & 1;    // ldmatrix 16B column select

    if (tid < 128) {
        *(float*)(smem + SM_SQI + tid * 4) = g_sq[m0 + tid];
        *(int*)(smem + SM_LABI + tid * 4) = lab[m0 + tid];
    } else {
        int q = tid - 128;
        *(float*)(smem + SM_SQJ + q * 4) = g_sq[n0 + q];
        *(int*)(smem + SM_LABJ + q * 4) = lab[n0 + q];
    }

    float acc[2][8][4];
    #pragma unroll
    for (int mt = 0; mt < 2; mt++)
        #pragma unroll
        for (int nt = 0; nt < 8; nt++)
            #pragma unroll
            for (int e = 0; e < 4; e++) acc[mt][nt][e] = 0.f;

    // 3-stage cp.async pipeline over 16 K-chunks of 32
    load_chunk(sb + SM_BUF, m0, n0, 0, tid);
    load_chunk(sb + SM_BUF + STAGE_BYTES, m0, n0, 32, tid);
    #pragma unroll 1
    for (int c = 0; c < 16; c++) {
        if (c + 2 < 16) {
            load_chunk(sb + SM_BUF + ((c + 2) % 3) * STAGE_BYTES, m0, n0, (c + 2) * 32, tid);
            CP_WAIT(2);
        } else if (c + 1 < 16) {
            CP_WAIT(1);
        } else {
            CP_WAIT(0);
        }
        __syncthreads();
        uint32_t Abase = sb + SM_BUF + (c % 3) * STAGE_BYTES;
        uint32_t Bbase = Abase + TILEB;
        #pragma unroll
        for (int ks = 0; ks < 2; ks++) {          // two k16 steps per 32-chunk
            uint32_t a[2][4];
            #pragma unroll
            for (int mt = 0; mt < 2; mt++)
                LDSM_X4(a[mt], Abase + (uint32_t)((mOff + mt * 16 + lrow) * ROWB + ks * 32 + lcol * 16));
            uint32_t b[4][4];
            #pragma unroll
            for (int p = 0; p < 4; p++)
                LDSM_X4(b[p], Bbase + (uint32_t)((nOff + p * 16 + lrow) * ROWB + ks * 32 + lcol * 16));
            #pragma unroll
            for (int p = 0; p < 4; p++) {
                // x4 on 16 n-rows: r0 = b0(nt=2p), r1 = b0(2p+1), r2 = b1(2p), r3 = b1(2p+1)
                mma_f16(acc[0][2 * p],     a[0], b[p][0], b[p][2]);
                mma_f16(acc[0][2 * p + 1], a[0], b[p][1], b[p][3]);
                mma_f16(acc[1][2 * p],     a[1], b[p][0], b[p][2]);
                mma_f16(acc[1][2 * p + 1], a[1], b[p][1], b[p][3]);
            }
        }
        __syncthreads();   // compute done before stage reuse
    }

    // ---------------- epilogue: d -> sd (smem), then row/col scans ----------
    float (*sd)[132] = (float (*)[132])(smem + SM_BUF);
    const float* s_sqi = (const float*)(smem + SM_SQI);
    const float* s_sqj = (const float*)(smem + SM_SQJ);
    const int* s_labi = (const int*)(smem + SM_LABI);
    const int* s_labj = (const int*)(smem + SM_LABJ);

    #pragma unroll
    for (int mt = 0; mt < 2; mt++) {
        int r0 = mOff + mt * 16 + grp;
        float sq0 = s_sqi[r0], sq1 = s_sqi[r0 + 8];
        #pragma unroll
        for (int nt = 0; nt < 8; nt++) {
            int c0 = nOff + nt * 8 + tig * 2;
            float sqa = s_sqj[c0], sqb = s_sqj[c0 + 1];
            const float* a = acc[mt][nt];
            sd[r0][c0]         = sqrtf(fmaxf(sq0 + sqa - 2.f * a[0], 0.f) + 1e-12f);
            sd[r0][c0 + 1]     = sqrtf(fmaxf(sq0 + sqb - 2.f * a[1], 0.f) + 1e-12f);
            sd[r0 + 8][c0]     = sqrtf(fmaxf(sq1 + sqa - 2.f * a[2], 0.f) + 1e-12f);
            sd[r0 + 8][c0 + 1] = sqrtf(fmaxf(sq1 + sqb - 2.f * a[3], 0.f) + 1e-12f);
        }
    }
    __syncthreads();

    if (tid < 128) {               // row scan: max over all j, min over diff-label j
        int r = tid, li = s_labi[r];
        float rmax = 0.f, nmin = 3.4028235e38f;
        #pragma unroll 4
        for (int j = 0; j < 128; j++) {
            float v = sd[r][j];
            rmax = fmaxf(rmax, v);
            if (li != s_labj[j]) nmin = fminf(nmin, v);
        }
        atomicMax((int*)&g_rowmax[m0 + r], __float_as_int(rmax));
        atomicMin((int*)&g_negmin[m0 + r], __float_as_int(nmin));
    } else if (!diag) {            // col scan (off-diagonal blocks only)
        int q = tid - 128, lj = s_labj[q];
        float cmax = 0.f, cnmin = 3.4028235e38f;
        #pragma unroll 4
        for (int r = 0; r < 128; r++) {
            float v = sd[r][q];
            cmax = fmaxf(cmax, v);
            if (s_labi[r] != lj) cnmin = fminf(cnmin, v);
        }
        atomicMax((int*)&g_rowmax[n0 + q], __float_as_int(cmax));
        atomicMin((int*)&g_negmin[n0 + q], __float_as_int(cnmin));
    }
}

// ---------------------------------------------------------------------------
// Kernel 2: per-class all-pairs (fp32 accum): hardest positive +
//   same-label correction  corr[i] = min_{j same label or j==i} (d(i,j)+maxd[j])
//   then pen[i] = relu(0.5 - min(negmin[i], corr[i]))
// ---------------------------------------------------------------------------
#define CSM_FEAT  0
#define CSM_MIDX  (CAP * 1024)
#define CSM_SQ    (CSM_MIDX + CAP * 4)
#define CSM_MAXD  (CSM_SQ + CAP * 4)
#define CSM_POS   (CSM_MAXD + CAP * 4)
#define CSM_CORR  (CSM_POS + CAP * 4)
#define CSM_CNT   (CSM_CORR + CAP * 4)
#define CSM_TOTAL (CSM_CNT + 16)

__global__ void class_kernel(const int* __restrict__ lab) {
    extern __shared__ char csm[];
    __half2* sfeat = (__half2*)(csm + CSM_FEAT);     // CAP x 256 half2
    int* midx = (int*)(csm + CSM_MIDX);
    float* s_sq = (float*)(csm + CSM_SQ);
    float* s_maxd = (float*)(csm + CSM_MAXD);
    int* s_pos = (int*)(csm + CSM_POS);
    int* s_corr = (int*)(csm + CSM_CORR);
    int* s_cnt = (int*)(csm + CSM_CNT);

    const int c = blockIdx.x;
    const int tid = (int)threadIdx.x;
    const int wid = tid >> 5, lane = tid & 31;

    if (tid == 0) *s_cnt = 0;
    __syncthreads();
    for (int j = tid; j < NROW; j += 256)
        if (lab[j] == c) { int p = atomicAdd(s_cnt, 1); if (p < CAP) midx[p] = j; }
    __syncthreads();
    int m = *s_cnt; if (m > CAP) m = CAP;

    for (int i = tid; i < m; i += 256) {
        int g = midx[i];
        s_sq[i] = g_sq[g];
        s_maxd[i] = g_rowmax[g];
        s_pos[i] = 0;
        s_corr[i] = 0x7f7fffff;  // FLT_MAX bits
    }
    __syncthreads();
    for (int idx = tid; idx < m * 64; idx += 256) {    // 64 uint4 per member
        int i = idx >> 6, w = idx & 63;
        ((uint4*)sfeat)[i * 64 + w] =
            *reinterpret_cast<const uint4*>(g_h + (size_t)midx[i] * DDIM + w * 8);
    }
    __syncthreads();

    // lower-triangle pairs (a >= b), both directions updated
    for (int a = wid; a < m; a += 8) {
        const __half2* fa = sfeat + a * 256;
        float sa = s_sq[a];
        for (int b = 0; b <= a; b++) {
            const __half2* fb = sfeat + b * 256;
            float dot = 0.f;
            #pragma unroll
            for (int k = 0; k < 8; k++) {
                float2 xa = __half22float2(fa[lane + k * 32]);
                float2 xb = __half22float2(fb[lane + k * 32]);
                dot = fmaf(xa.x, xb.x, dot);
                dot = fmaf(xa.y, xb.y, dot);
            }
            #pragma unroll
            for (int o = 16; o > 0; o >>= 1) dot += __shfl_xor_sync(0xffffffffu, dot, o);
            if (lane == 0) {
                float d = sqrtf(fmaxf(sa + s_sq[b] - 2.f * dot, 0.f) + 1e-12f);
                int di = __float_as_int(d);
                if (a != b) {
                    atomicMax(&s_pos[a], di);
                    atomicMax(&s_pos[b], di);
                    atomicMin(&s_corr[a], __float_as_int(d + s_maxd[b]));
                    atomicMin(&s_corr[b], __float_as_int(d + s_maxd[a]));
                } else {
                    atomicMin(&s_corr[a], __float_as_int(d + s_maxd[a]));
                }
            }
        }
    }
    __syncthreads();

    for (int i = tid; i < m; i += 256) {
        int g = midx[i];
        g_posmax[g] = __int_as_float(s_pos[i]);
        float hn = fminf(g_negmin[g], __int_as_float(s_corr[i]));
        g_pen[g] = fmaxf(0.5f - hn, 0.f);
    }
}

// ---------------------------------------------------------------------------
// Kernel 3: final deterministic reduction -> scalar loss
// ---------------------------------------------------------------------------
__global__ void final_kernel(float* __restrict__ out) {
    float s = 0.f;
    for (int i = threadIdx.x; i < NROW; i += blockDim.x)
        s += g_posmax[i] + g_pen[i];
    #pragma unroll
    for (int o = 16; o > 0; o >>= 1) s += __shfl_xor_sync(0xffffffffu, s, o);
    __shared__ float ws[32];
    if ((threadIdx.x & 31) == 0) ws[threadIdx.x >> 5] = s;
    __syncthreads();
    if (threadIdx.x == 0) {
        float t = 0.f;
        #pragma unroll
        for (int w = 0; w < 32; w++) t += ws[w];
        out[0] = t / (float)NROW;
    }
}

// ---------------------------------------------------------------------------
extern "C" void kernel_launch(void* const* d_in, const int* in_sizes, int n_in,
                              void* d_out, int out_size) {
    const float* X = (const float*)d_in[0];
    const int* lab = (const int*)d_in[1];
    float* out = (float*)d_out;

    cudaFuncSetAttribute(dist_kernel, cudaFuncAttributeMaxDynamicSharedMemorySize, SMEM_TOTAL);
    cudaFuncSetAttribute(class_kernel, cudaFuncAttributeMaxDynamicSharedMemorySize, CSM_TOTAL);

    conv_kernel<<<NROW, 128>>>(X);
    dist_kernel<<<dim3(32, 32), 256, SMEM_TOTAL>>>(lab);
    class_kernel<<<64, 256, CSM_TOTAL>>>(lab);
    final_kernel<<<1, 1024>>>(out);
}

// round 6
// speedup vs baseline: 2.8316x; 2.8316x over previous
#include <cuda_runtime.h>
#include <cuda_fp16.h>
#include <cstdint>

#define NROW 4096
#define DDIM 512

// -------------------------- device scratch (no allocs) ----------------------
__device__ float g_sq[NROW];
__device__ float g_rowmax[NROW];   // max_distance per row (idempotent atomicMax, zero-init)
__device__ float g_posmax[NROW];   // hardest positive per row (idempotent atomicMax)
__device__ float g_pen[NROW];      // relu(margin - hardest_negative)
__device__ float g_dist[(size_t)NROW * NROW];   // 64 MB dist matrix
__device__ __half g_h[(size_t)NROW * DDIM];     // fp16 features

// -------------------------- PTX helpers -------------------------------------
__device__ __forceinline__ uint32_t smem_u32(const void* p) {
    uint32_t a;
    asm("{ .reg .u64 t; cvta.to.shared.u64 t, %1; cvt.u32.u64 %0, t; }" : "=r"(a) : "l"(p));
    return a;
}

#define CP_ASYNC16(dst, src) \
    asm volatile("cp.async.cg.shared.global [%0], [%1], 16;" :: "r"(dst), "l"(src) : "memory")
#define CP_COMMIT() asm volatile("cp.async.commit_group;" ::: "memory")
#define CP_WAIT(n)  asm volatile("cp.async.wait_group %0;" :: "n"(n) : "memory")

#define LDSM_X4(R, addr) \
    asm volatile("ldmatrix.sync.aligned.m8n8.x4.shared.b16 {%0,%1,%2,%3}, [%4];" \
        : "=r"((R)[0]), "=r"((R)[1]), "=r"((R)[2]), "=r"((R)[3]) : "r"(addr))

// D(16x8,f32) += A(16x16 f16, row) * B(16x8 f16, col: B[n][k])
__device__ __forceinline__ void mma_f16(float* d, const uint32_t* a, uint32_t b0, uint32_t b1) {
    asm volatile(
        "mma.sync.aligned.m16n8k16.row.col.f32.f16.f16.f32 "
        "{%0,%1,%2,%3}, {%4,%5,%6,%7}, {%8,%9}, {%0,%1,%2,%3};"
        : "+f"(d[0]), "+f"(d[1]), "+f"(d[2]), "+f"(d[3])
        : "r"(a[0]), "r"(a[1]), "r"(a[2]), "r"(a[3]), "r"(b0), "r"(b1));
}

// -------------------------- dist kernel SMEM layout -------------------------
// [0]    s_sqi[128]  [512] s_sqj[128]  [1024] s_labi[128]  [1536] s_labj[128]
// [2048] 3 stages x (A[128][40h] + B[128][40h]) fp16   (20480 B per stage)
//        epilogue reuses [2048] as sd[128][129] fp32   (66048 B)
#define SM_SQI   0
#define SM_SQJ   512
#define SM_LABI  1024
#define SM_LABJ  1536
#define SM_BUF   2048
#define ROWB     80                // bytes per smem tile row (32 halves + 8 pad)
#define TILEB    (128 * ROWB)      // 10240
#define STAGE_BYTES (2 * TILEB)    // 20480
#define SMEM_TOTAL (SM_BUF + 128 * 129 * 4)   // 68096 > 2048 + 3*20480 = 63488

// ---------------------------------------------------------------------------
// Kernel 0: fp16 convert + squared norms
// ---------------------------------------------------------------------------
__global__ void conv_kernel(const float* __restrict__ X) {
    int row = blockIdx.x;
    int t = threadIdx.x;           // 0..127, one float4 each
    const float4* xr = reinterpret_cast<const float4*>(X + (size_t)row * DDIM);
    float4 v = xr[t];
    float vv[4] = {v.x, v.y, v.z, v.w};
    float s = 0.f;
    __half h[4];
    #pragma unroll
    for (int k = 0; k < 4; k++) { s += vv[k] * vv[k]; h[k] = __float2half_rn(vv[k]); }
    *reinterpret_cast<uint2*>(g_h + (size_t)row * DDIM + t * 4) = *reinterpret_cast<uint2*>(h);
    #pragma unroll
    for (int q = 16; q > 0; q >>= 1) s += __shfl_xor_sync(0xffffffffu, s, q);
    __shared__ float ws[4];
    if ((t & 31) == 0) ws[t >> 5] = s;
    __syncthreads();
    if (t == 0) g_sq[row] = ws[0] + ws[1] + ws[2] + ws[3];
}

// ---------------------------------------------------------------------------
// Kernel 1: fp16 mma.sync Gram + distance epilogue (upper-triangular tiles)
// ---------------------------------------------------------------------------
__device__ __forceinline__ void load_chunk(uint32_t stage_base, int m0, int n0, int k0, int tid) {
    #pragma unroll
    for (int t = 0; t < 2; t++) {        // 0 = A rows (m0), 1 = B rows (n0)
        int r0 = t ? n0 : m0;
        uint32_t dbase = stage_base + t * TILEB;
        #pragma unroll
        for (int q = 0; q < 2; q++) {
            int idx = q * 256 + tid;     // 0..511
            int row = idx >> 2;
            int seg = idx & 3;           // 4 x 16B = 32 halves per row
            const __half* gs = g_h + (size_t)(r0 + row) * DDIM + k0 + seg * 8;
            CP_ASYNC16(dbase + (uint32_t)(row * ROWB + seg * 16), gs);
        }
    }
    CP_COMMIT();
}

__global__ __launch_bounds__(256, 2) void dist_kernel(const int* __restrict__ lab) {
    const int bi = blockIdx.y, bj = blockIdx.x;
    if (bj < bi) return;                 // symmetric: upper triangle only
    const int m0 = bi * 128, n0 = bj * 128;
    const bool diag = (bi == bj);

    extern __shared__ char smem[];
    const uint32_t sb = smem_u32(smem);
    const int tid = (int)threadIdx.x;
    const int wid = tid >> 5, lane = tid & 31;
    const int grp = lane >> 2, tig = lane & 3;
    const int mOff = (wid >> 1) * 32;    // warp tile: 32 x 64
    const int nOff = (wid & 1) * 64;
    const int lrow = lane & 15;          // ldmatrix row within 16-row group
    const int lcol = (lane >> 4) & 1;    // ldmatrix 16B column select

    if (tid < 128) {
        *(float*)(smem + SM_SQI + tid * 4) = g_sq[m0 + tid];
        *(int*)(smem + SM_LABI + tid * 4) = lab[m0 + tid];
    } else {
        int q = tid - 128;
        *(float*)(smem + SM_SQJ + q * 4) = g_sq[n0 + q];
        *(int*)(smem + SM_LABJ + q * 4) = lab[n0 + q];
    }

    float acc[2][8][4];
    #pragma unroll
    for (int mt = 0; mt < 2; mt++)
        #pragma unroll
        for (int nt = 0; nt < 8; nt++)
            #pragma unroll
            for (int e = 0; e < 4; e++) acc[mt][nt][e] = 0.f;

    // 3-stage cp.async pipeline over 16 K-chunks of 32
    load_chunk(sb + SM_BUF, m0, n0, 0, tid);
    load_chunk(sb + SM_BUF + STAGE_BYTES, m0, n0, 32, tid);
    #pragma unroll 1
    for (int c = 0; c < 16; c++) {
        if (c + 2 < 16) {
            load_chunk(sb + SM_BUF + ((c + 2) % 3) * STAGE_BYTES, m0, n0, (c + 2) * 32, tid);
            CP_WAIT(2);
        } else if (c + 1 < 16) {
            CP_WAIT(1);
        } else {
            CP_WAIT(0);
        }
        __syncthreads();
        uint32_t Abase = sb + SM_BUF + (c % 3) * STAGE_BYTES;
        uint32_t Bbase = Abase + TILEB;
        #pragma unroll
        for (int ks = 0; ks < 2; ks++) {          // two k16 steps per 32-chunk
            uint32_t a[2][4];
            #pragma unroll
            for (int mt = 0; mt < 2; mt++)
                LDSM_X4(a[mt], Abase + (uint32_t)((mOff + mt * 16 + lrow) * ROWB + ks * 32 + lcol * 16));
            uint32_t b[4][4];
            #pragma unroll
            for (int p = 0; p < 4; p++)
                LDSM_X4(b[p], Bbase + (uint32_t)((nOff + p * 16 + lrow) * ROWB + ks * 32 + lcol * 16));
            #pragma unroll
            for (int p = 0; p < 4; p++) {
                mma_f16(acc[0][2 * p],     a[0], b[p][0], b[p][2]);
                mma_f16(acc[0][2 * p + 1], a[0], b[p][1], b[p][3]);
                mma_f16(acc[1][2 * p],     a[1], b[p][0], b[p][2]);
                mma_f16(acc[1][2 * p + 1], a[1], b[p][1], b[p][3]);
            }
        }
        __syncthreads();   // compute done before stage reuse
    }

    // ---------------- epilogue: d -> sd (smem), then row/col scans ----------
    float (*sd)[129] = (float (*)[129])(smem + SM_BUF);
    const float* s_sqi = (const float*)(smem + SM_SQI);
    const float* s_sqj = (const float*)(smem + SM_SQJ);
    const int* s_labi = (const int*)(smem + SM_LABI);
    const int* s_labj = (const int*)(smem + SM_LABJ);

    #pragma unroll
    for (int mt = 0; mt < 2; mt++) {
        int r0 = mOff + mt * 16 + grp;
        float sq0 = s_sqi[r0], sq1 = s_sqi[r0 + 8];
        #pragma unroll
        for (int nt = 0; nt < 8; nt++) {
            int c0 = nOff + nt * 8 + tig * 2;
            float sqa = s_sqj[c0], sqb = s_sqj[c0 + 1];
            const float* a = acc[mt][nt];
            sd[r0][c0]         = sqrtf(fmaxf(sq0 + sqa - 2.f * a[0], 0.f) + 1e-12f);
            sd[r0][c0 + 1]     = sqrtf(fmaxf(sq0 + sqb - 2.f * a[1], 0.f) + 1e-12f);
            sd[r0 + 8][c0]     = sqrtf(fmaxf(sq1 + sqa - 2.f * a[2], 0.f) + 1e-12f);
            sd[r0 + 8][c0 + 1] = sqrtf(fmaxf(sq1 + sqb - 2.f * a[3], 0.f) + 1e-12f);
        }
    }
    __syncthreads();

    // row stats (i-range) and column stats (j-range)
    if (tid < 128) {
        int r = tid, li = s_labi[r];
        float rmax = 0.f, pmax = 0.f;
        #pragma unroll 4
        for (int j = 0; j < 128; j++) {
            float v = sd[r][j];
            rmax = fmaxf(rmax, v);
            if (li == s_labj[j] && (m0 + r) != (n0 + j)) pmax = fmaxf(pmax, v);
        }
        atomicMax((int*)&g_rowmax[m0 + r], __float_as_int(rmax));
        atomicMax((int*)&g_posmax[m0 + r], __float_as_int(pmax));
    } else if (!diag) {
        int q = tid - 128, ljq = s_labj[q];
        float cmax = 0.f, cpmax = 0.f;
        #pragma unroll 4
        for (int r = 0; r < 128; r++) {
            float v = sd[r][q];
            cmax = fmaxf(cmax, v);
            if (s_labi[r] == ljq && (m0 + r) != (n0 + q)) cpmax = fmaxf(cpmax, v);
        }
        atomicMax((int*)&g_rowmax[n0 + q], __float_as_int(cmax));
        atomicMax((int*)&g_posmax[n0 + q], __float_as_int(cpmax));
    }

    // stores: direct block + transposed block
    for (int idx = tid; idx < 4096; idx += 256) {
        int r = idx >> 5, c4 = (idx & 31) * 4;
        float4 v = make_float4(sd[r][c4], sd[r][c4 + 1], sd[r][c4 + 2], sd[r][c4 + 3]);
        *reinterpret_cast<float4*>(&g_dist[(size_t)(m0 + r) * NROW + n0 + c4]) = v;
    }
    if (!diag) {
        for (int idx = tid; idx < 4096; idx += 256) {
            int q = idx >> 5, r4 = (idx & 31) * 4;
            float4 v = make_float4(sd[r4][q], sd[r4 + 1][q], sd[r4 + 2][q], sd[r4 + 3][q]);
            *reinterpret_cast<float4*>(&g_dist[(size_t)(n0 + q) * NROW + m0 + r4]) = v;
        }
    }
}

// ---------------------------------------------------------------------------
// Kernel 2: hardest negative per row.
//   negative_distance[i][j] = dist[i][j] + max_distance[j] * not_negative[i][j]
// ---------------------------------------------------------------------------
__global__ void hneg_kernel(const int* __restrict__ lab) {
    const int i = blockIdx.x;
    const int li = lab[i];
    const float* drow = g_dist + (size_t)i * NROW;
    float mn = 3.4028235e38f;
    for (int j = threadIdx.x; j < NROW; j += blockDim.x) {
        float v = drow[j];
        if (lab[j] == li || j == i) v += g_rowmax[j];
        mn = fminf(mn, v);
    }
    #pragma unroll
    for (int o = 16; o > 0; o >>= 1) mn = fminf(mn, __shfl_xor_sync(0xffffffffu, mn, o));
    __shared__ float ws[8];
    if ((threadIdx.x & 31) == 0) ws[threadIdx.x >> 5] = mn;
    __syncthreads();
    if (threadIdx.x == 0) {
        float m = ws[0];
        #pragma unroll
        for (int w = 1; w < 8; w++) m = fminf(m, ws[w]);
        g_pen[i] = fmaxf(0.5f - m, 0.f);
    }
}

// ---------------------------------------------------------------------------
// Kernel 3: final deterministic reduction -> scalar loss
// ---------------------------------------------------------------------------
__global__ void final_kernel(float* __restrict__ out) {
    float s = 0.f;
    for (int i = threadIdx.x; i < NROW; i += blockDim.x)
        s += g_posmax[i] + g_pen[i];
    #pragma unroll
    for (int o = 16; o > 0; o >>= 1) s += __shfl_xor_sync(0xffffffffu, s, o);
    __shared__ float ws[32];
    if ((threadIdx.x & 31) == 0) ws[threadIdx.x >> 5] = s;
    __syncthreads();
    if (threadIdx.x == 0) {
        float t = 0.f;
        #pragma unroll
        for (int w = 0; w < 32; w++) t += ws[w];
        out[0] = t / (float)NROW;
    }
}

// ---------------------------------------------------------------------------
extern "C" void kernel_launch(void* const* d_in, const int* in_sizes, int n_in,
                              void* d_out, int out_size) {
    const float* X = (const float*)d_in[0];
    const int* lab = (const int*)d_in[1];
    float* out = (float*)d_out;

    cudaFuncSetAttribute(dist_kernel, cudaFuncAttributeMaxDynamicSharedMemorySize, SMEM_TOTAL);

    conv_kernel<<<NROW, 128>>>(X);
    dist_kernel<<<dim3(32, 32), 256, SMEM_TOTAL>>>(lab);
    hneg_kernel<<<NROW, 256>>>(lab);
    final_kernel<<<1, 1024>>>(out);
}